// round 3
// baseline (speedup 1.0000x reference)
#include <cuda_runtime.h>

// Problem constants (fixed shapes from reference)
#define NBATCH 2
#define LSEQ   2048
#define EMB    1024
#define NHEAD  16
#define HDIM   64

static __device__ float g_q[(size_t)NBATCH * NHEAD * LSEQ * HDIM];   // [n,h,l,d]
static __device__ float g_k[(size_t)NBATCH * NHEAD * LSEQ * HDIM];   // [n,h,l,d]
static __device__ float g_v[(size_t)NBATCH * NHEAD * LSEQ * HDIM];   // [n,h,l,d]
static __device__ float g_att[(size_t)NBATCH * LSEQ * EMB];          // [n,l,e]

// ---------------------------------------------------------------------------
// Kernel A: fused QKV projection.
// View input [N,L,E] as [N*L*H, 64] (e = h*64+d contiguous).
// y[r,d] = sum_e x[r,e] * W[d,e].  Output stored in [n,h,l,d] layout.
// Block: 64 rows x 64 cols, 256 threads, 4x4 register tile per thread.
// Xs: stride 64 (broadcast reads, float4 stores). Ws: stride 66 (16-row
// strided reads -> conflict-free banks (2r+e)%32, float2 loads 8B-aligned).
// ---------------------------------------------------------------------------
__device__ __forceinline__ void proj_one(
    const float* __restrict__ X, const float* __restrict__ W, float* __restrict__ O,
    float (&Ws)[64][66], float (&Xs)[64][64],
    int t, int tx, int ty, int r0)
{
    __syncthreads();  // protect smem reuse across calls
    const float4* w4 = reinterpret_cast<const float4*>(W);
    const float4* x4 = reinterpret_cast<const float4*>(X + (size_t)r0 * HDIM);
#pragma unroll
    for (int i = 0; i < 4; i++) {
        int idx = t + i * 256;          // 0..1023 float4 ids (64 rows x 16 f4)
        int row = idx >> 4;
        int col = (idx & 15) << 2;
        float4 wv = w4[idx];
        Ws[row][col]   = wv.x; Ws[row][col+1] = wv.y;
        Ws[row][col+2] = wv.z; Ws[row][col+3] = wv.w;
        *reinterpret_cast<float4*>(&Xs[row][col]) = x4[idx];
    }
    __syncthreads();

    float acc[4][4];
#pragma unroll
    for (int i = 0; i < 4; i++)
#pragma unroll
        for (int j = 0; j < 4; j++) acc[i][j] = 0.f;

#pragma unroll 8
    for (int e = 0; e < 64; e += 2) {
        float2 a[4], b[4];
#pragma unroll
        for (int i = 0; i < 4; i++)
            a[i] = *reinterpret_cast<const float2*>(&Xs[ty + 16 * i][e]);
#pragma unroll
        for (int j = 0; j < 4; j++)
            b[j] = *reinterpret_cast<const float2*>(&Ws[tx + 16 * j][e]);
#pragma unroll
        for (int i = 0; i < 4; i++)
#pragma unroll
            for (int j = 0; j < 4; j++) {
                acc[i][j] += a[i].x * b[j].x;
                acc[i][j] += a[i].y * b[j].y;
            }
    }

#pragma unroll
    for (int i = 0; i < 4; i++) {
        int r  = r0 + ty + 16 * i;      // r = (n*L + l)*H + h
        int h  = r & (NHEAD - 1);
        int nl = r >> 4;
        int l  = nl & (LSEQ - 1);
        int n  = nl >> 11;
        float* o = O + (((size_t)(n * NHEAD + h) * LSEQ + l) * HDIM);
#pragma unroll
        for (int j = 0; j < 4; j++) o[tx + 16 * j] = acc[i][j];
    }
}

__global__ __launch_bounds__(256) void qkv_proj_kernel(
    const float* __restrict__ values, const float* __restrict__ keys,
    const float* __restrict__ query,
    const float* __restrict__ Wv, const float* __restrict__ Wk,
    const float* __restrict__ Wq)
{
    __shared__ float Ws[64][66];
    __shared__ float Xs[64][64];
    int t  = threadIdx.x;
    int tx = t & 15, ty = t >> 4;
    int r0 = blockIdx.x * 64;
    proj_one(query,  Wq, g_q, Ws, Xs, t, tx, ty, r0);
    proj_one(keys,   Wk, g_k, Ws, Xs, t, tx, ty, r0);
    proj_one(values, Wv, g_v, Ws, Xs, t, tx, ty, r0);
}

// ---------------------------------------------------------------------------
// Kernel B: flash attention (online softmax), fp32.
// One block = one (n,h), 64 q rows. K tiles of 32. 256 threads.
// Per thread: S tile 4x2 (q rows {ty+16i}, k cols {tx,tx+16}),
//             O tile 4x4 (contiguous d cols {4*tx+c}).
// Qs stride 64 (broadcast reads, float4 stores); Ks stride 66 (strided reads).
// Mask: key-position mask, masked scores -> -1e20 (equivalent to reference's
// mask-then-scale under softmax). Scale = 1/sqrt(EMB) = 1/32.
// ---------------------------------------------------------------------------
__global__ __launch_bounds__(256) void attn_kernel(const int* __restrict__ mask)
{
    __shared__ float Qs[64][64];
    __shared__ float Ks[32][66];
    __shared__ float Vs[32][64];
    __shared__ float Ss[64][33];
    __shared__ int   mk[32];

    const float SCALE = 0.03125f;   // 1/sqrt(1024)

    int t  = threadIdx.x;
    int tx = t & 15, ty = t >> 4;
    int q0 = blockIdx.x * 64;
    int nh = blockIdx.y;
    int n  = nh >> 4;
    int h  = nh & 15;

    const size_t base = (size_t)nh * LSEQ * HDIM;
    const float* qb = g_q + base;
    const float* kb = g_k + base;
    const float* vb = g_v + base;

    // load Q tile (64x64), direct float4 smem stores
    {
        const float4* q4 = reinterpret_cast<const float4*>(qb + (size_t)q0 * HDIM);
        float4* qs4 = reinterpret_cast<float4*>(&Qs[0][0]);
#pragma unroll
        for (int i = 0; i < 4; i++) qs4[t + i * 256] = q4[t + i * 256];
    }

    float m_i[4], l_i[4], o[4][4];
#pragma unroll
    for (int i = 0; i < 4; i++) {
        m_i[i] = -3.0e38f;
        l_i[i] = 0.f;
#pragma unroll
        for (int j = 0; j < 4; j++) o[i][j] = 0.f;
    }

    for (int kt = 0; kt < LSEQ / 32; kt++) {
        int k0 = kt * 32;
        __syncthreads();   // prior iteration done with Ks/Vs/Ss/mk (also orders Qs on iter 0)
        {
            const float4* k4 = reinterpret_cast<const float4*>(kb + (size_t)k0 * HDIM);
            const float4* v4 = reinterpret_cast<const float4*>(vb + (size_t)k0 * HDIM);
#pragma unroll
            for (int i = 0; i < 2; i++) {
                int idx = t + i * 256;      // 0..511 (32 rows x 16 f4)
                int row = idx >> 4;
                int col = (idx & 15) << 2;
                float4 kv = k4[idx];
                Ks[row][col]   = kv.x; Ks[row][col+1] = kv.y;
                Ks[row][col+2] = kv.z; Ks[row][col+3] = kv.w;
                reinterpret_cast<float4*>(&Vs[0][0])[idx] = v4[idx];
            }
            if (t < 32) mk[t] = __ldg(&mask[n * LSEQ + k0 + t]);
        }
        __syncthreads();

        // S = Q @ K^T  (4x2 per thread), reduction dim in float2 pairs
        float s[4][2];
#pragma unroll
        for (int i = 0; i < 4; i++) { s[i][0] = 0.f; s[i][1] = 0.f; }
#pragma unroll 8
        for (int e = 0; e < 64; e += 2) {
            float2 a[4], b0, b1;
#pragma unroll
            for (int i = 0; i < 4; i++)
                a[i] = *reinterpret_cast<const float2*>(&Qs[ty + 16 * i][e]);
            b0 = *reinterpret_cast<const float2*>(&Ks[tx][e]);
            b1 = *reinterpret_cast<const float2*>(&Ks[tx + 16][e]);
#pragma unroll
            for (int i = 0; i < 4; i++) {
                s[i][0] += a[i].x * b0.x;
                s[i][0] += a[i].y * b0.y;
                s[i][1] += a[i].x * b1.x;
                s[i][1] += a[i].y * b1.y;
            }
        }

        int keep0 = mk[tx];
        int keep1 = mk[tx + 16];
        float p[4][2], mt[4];
#pragma unroll
        for (int i = 0; i < 4; i++) {
            float v0 = keep0 ? s[i][0] * SCALE : -1.0e20f;
            float v1 = keep1 ? s[i][1] * SCALE : -1.0e20f;
            p[i][0] = v0; p[i][1] = v1;
            mt[i] = fmaxf(v0, v1);
        }
        // row max across the 16 lanes that share a q row
#pragma unroll
        for (int off = 8; off >= 1; off >>= 1) {
#pragma unroll
            for (int i = 0; i < 4; i++)
                mt[i] = fmaxf(mt[i], __shfl_xor_sync(0xffffffffu, mt[i], off));
        }
        float rsum[4];
#pragma unroll
        for (int i = 0; i < 4; i++) {
            float mn = fmaxf(m_i[i], mt[i]);
            float c  = __expf(m_i[i] - mn);
            m_i[i]   = mn;
            p[i][0]  = __expf(p[i][0] - mn);
            p[i][1]  = __expf(p[i][1] - mn);
            rsum[i]  = p[i][0] + p[i][1];
            l_i[i]  *= c;
#pragma unroll
            for (int j = 0; j < 4; j++) o[i][j] *= c;
        }
#pragma unroll
        for (int off = 8; off >= 1; off >>= 1) {
#pragma unroll
            for (int i = 0; i < 4; i++)
                rsum[i] += __shfl_xor_sync(0xffffffffu, rsum[i], off);
        }
#pragma unroll
        for (int i = 0; i < 4; i++) {
            l_i[i] += rsum[i];
            Ss[ty + 16 * i][tx]      = p[i][0];
            Ss[ty + 16 * i][tx + 16] = p[i][1];
        }
        __syncthreads();

        // O += P @ V   (each thread: 4 q rows x contiguous d cols 4*tx..4*tx+3)
#pragma unroll 8
        for (int j = 0; j < 32; j++) {
            float4 vv = *reinterpret_cast<const float4*>(&Vs[j][tx << 2]);
#pragma unroll
            for (int i = 0; i < 4; i++) {
                float ps = Ss[ty + 16 * i][j];
                o[i][0] += ps * vv.x;
                o[i][1] += ps * vv.y;
                o[i][2] += ps * vv.z;
                o[i][3] += ps * vv.w;
            }
        }
    }

    // epilogue: normalize, write to g_att in [n,l,e] layout (vector store)
#pragma unroll
    for (int i = 0; i < 4; i++) {
        int qpos = q0 + ty + 16 * i;
        float inv = 1.0f / l_i[i];
        float* op = g_att + ((size_t)n * LSEQ + qpos) * EMB + h * HDIM + (tx << 2);
        *reinterpret_cast<float4*>(op) =
            make_float4(o[i][0] * inv, o[i][1] * inv, o[i][2] * inv, o[i][3] * inv);
    }
}

// ---------------------------------------------------------------------------
// Kernel C: output projection: out[r,c] = bo[c] + sum_e A[r,e]*Wo[c,e]
// A = g_att [4096,1024]. Block: 64x64 C tile, e tiles of 64, 256 threads.
// As stride 64 (broadcast reads, float4 stores); Bs stride 66 (strided reads).
// ---------------------------------------------------------------------------
__global__ __launch_bounds__(256) void out_proj_kernel(
    const float* __restrict__ Wo, const float* __restrict__ bo,
    float* __restrict__ out)
{
    __shared__ float As[64][64];
    __shared__ float Bs[64][66];
    int t  = threadIdx.x;
    int tx = t & 15, ty = t >> 4;
    int c0 = blockIdx.x * 64;
    int r0 = blockIdx.y * 64;

    float acc[4][4];
#pragma unroll
    for (int i = 0; i < 4; i++)
#pragma unroll
        for (int j = 0; j < 4; j++) acc[i][j] = 0.f;

    for (int et = 0; et < EMB / 64; et++) {
        int e0 = et * 64;
        __syncthreads();
#pragma unroll
        for (int i = 0; i < 4; i++) {
            int idx  = t + i * 256;      // 0..1023 (64 rows x 16 f4)
            int row  = idx >> 4;
            int col4 = idx & 15;
            *reinterpret_cast<float4*>(&As[row][col4 * 4]) =
                *reinterpret_cast<const float4*>(
                    g_att + (size_t)(r0 + row) * EMB + e0 + col4 * 4);
            float4 bv = *reinterpret_cast<const float4*>(
                Wo + (size_t)(c0 + row) * EMB + e0 + col4 * 4);
            int col = col4 * 4;
            Bs[row][col]   = bv.x; Bs[row][col+1] = bv.y;
            Bs[row][col+2] = bv.z; Bs[row][col+3] = bv.w;
        }
        __syncthreads();
#pragma unroll 8
        for (int e = 0; e < 64; e += 2) {
            float2 a[4], b[4];
#pragma unroll
            for (int i = 0; i < 4; i++)
                a[i] = *reinterpret_cast<const float2*>(&As[ty + 16 * i][e]);
#pragma unroll
            for (int j = 0; j < 4; j++)
                b[j] = *reinterpret_cast<const float2*>(&Bs[tx + 16 * j][e]);
#pragma unroll
            for (int i = 0; i < 4; i++)
#pragma unroll
                for (int j = 0; j < 4; j++) {
                    acc[i][j] += a[i].x * b[j].x;
                    acc[i][j] += a[i].y * b[j].y;
                }
        }
    }

#pragma unroll
    for (int i = 0; i < 4; i++) {
        int r = r0 + ty + 16 * i;
#pragma unroll
        for (int j = 0; j < 4; j++) {
            int c = c0 + tx + 16 * j;
            out[(size_t)r * EMB + c] = acc[i][j] + bo[c];
        }
    }
}

// ---------------------------------------------------------------------------
// Launch
// ---------------------------------------------------------------------------
extern "C" void kernel_launch(void* const* d_in, const int* in_sizes, int n_in,
                              void* d_out, int out_size)
{
    const float* values = (const float*)d_in[0];
    const float* keys   = (const float*)d_in[1];
    const float* query  = (const float*)d_in[2];
    const int*   mask   = (const int*)d_in[3];
    const float* Wv     = (const float*)d_in[4];
    const float* Wk     = (const float*)d_in[5];
    const float* Wq     = (const float*)d_in[6];
    const float* Wo     = (const float*)d_in[7];
    const float* bo     = (const float*)d_in[8];
    float* out = (float*)d_out;

    // A: 65536 rows / 64 per block
    qkv_proj_kernel<<<(NBATCH * LSEQ * NHEAD) / 64, 256>>>(
        values, keys, query, Wv, Wk, Wq);
    // B: (q tiles, n*h)
    attn_kernel<<<dim3(LSEQ / 64, NBATCH * NHEAD), 256>>>(mask);
    // C: (col tiles, row tiles)
    out_proj_kernel<<<dim3(EMB / 64, (NBATCH * LSEQ) / 64), 256>>>(Wo, bo, out);
}

// round 16
// speedup vs baseline: 1.7311x; 1.7311x over previous
#include <cuda_runtime.h>

// Problem constants (fixed shapes from reference)
#define NBATCH 2
#define LSEQ   2048
#define EMB    1024
#define NHEAD  16
#define HDIM   64

typedef unsigned long long u64;

static __device__ float g_q[(size_t)NBATCH * NHEAD * LSEQ * HDIM];   // [n,h,l,d]
static __device__ float g_k[(size_t)NBATCH * NHEAD * LSEQ * HDIM];   // [n,h,lc,d] compacted
static __device__ float g_v[(size_t)NBATCH * NHEAD * LSEQ * HDIM];   // [n,h,lc,d] compacted
static __device__ float g_att[(size_t)NBATCH * LSEQ * EMB];          // [n,l,e]
static __device__ int   g_pos[NBATCH * LSEQ];                        // compact position per key
static __device__ int   g_cnt[NBATCH];                               // kept keys per batch

// ---- packed f32x2 helpers (FFMA2 path; ptxas never emits these from C++) ----
__device__ __forceinline__ void ffma2(u64& d, u64 a, u64 b) {
    asm("fma.rn.f32x2 %0, %1, %2, %0;" : "+l"(d) : "l"(a), "l"(b));
}
__device__ __forceinline__ void fmul2(u64& d, u64 a, u64 b) {
    asm("mul.rn.f32x2 %0, %1, %2;" : "=l"(d) : "l"(a), "l"(b));
}
__device__ __forceinline__ float hadd2(u64 v) {
    float x, y;
    asm("mov.b64 {%0,%1}, %2;" : "=f"(x), "=f"(y) : "l"(v));
    return x + y;
}
__device__ __forceinline__ u64 pack2(float x, float y) {
    u64 v; asm("mov.b64 %0, {%1,%2};" : "=l"(v) : "f"(x), "f"(y)); return v;
}
__device__ __forceinline__ u64 lds2(const float* p) {   // 8B-aligned smem pair
    return *reinterpret_cast<const u64*>(p);
}

// ---------------------------------------------------------------------------
// Kernel 0: mask scan. One block per batch; exclusive prefix over 2048 mask
// ints -> compact position per kept key + total count.
// ---------------------------------------------------------------------------
__global__ __launch_bounds__(256) void mask_scan_kernel(const int* __restrict__ mask)
{
    __shared__ int sums[256];
    int n = blockIdx.x;
    int t = threadIdx.x;
    int local[8], s = 0;
#pragma unroll
    for (int i = 0; i < 8; i++) {
        local[i] = (mask[n * LSEQ + t * 8 + i] != 0) ? 1 : 0;
        s += local[i];
    }
    sums[t] = s;
    __syncthreads();
    for (int off = 1; off < 256; off <<= 1) {
        int v = (t >= off) ? sums[t - off] : 0;
        __syncthreads();
        sums[t] += v;
        __syncthreads();
    }
    int run = sums[t] - s;   // exclusive base for this thread's 8 elements
#pragma unroll
    for (int i = 0; i < 8; i++) {
        g_pos[n * LSEQ + t * 8 + i] = run;
        run += local[i];
    }
    if (t == 255) g_cnt[n] = sums[255];
}

// ---------------------------------------------------------------------------
// Kernel A: fused QKV projection.
// View input [N,L,E] as [N*L*H, 64] (e = h*64+d contiguous).
// y[r,d] = sum_e x[r,e] * W[d,e].
// Q rows stored at l; K/V rows stored COMPACTED at lc=g_pos[n,l] (kept only).
// Block: 64 rows x 64 cols, 256 threads, 4x4 register tile, f32x2 reduction.
// ---------------------------------------------------------------------------
__device__ __forceinline__ void proj_one(
    const float* __restrict__ X, const float* __restrict__ W, float* __restrict__ O,
    const int* __restrict__ mask, bool compact,
    float (&Ws)[64][66], float (&Xs)[64][64],
    int t, int tx, int ty, int r0)
{
    __syncthreads();  // protect smem reuse across calls
    const float4* w4 = reinterpret_cast<const float4*>(W);
    const float4* x4 = reinterpret_cast<const float4*>(X + (size_t)r0 * HDIM);
#pragma unroll
    for (int i = 0; i < 4; i++) {
        int idx = t + i * 256;          // 0..1023 float4 ids (64 rows x 16 f4)
        int row = idx >> 4;
        int col = (idx & 15) << 2;
        float4 wv = w4[idx];
        Ws[row][col]   = wv.x; Ws[row][col+1] = wv.y;
        Ws[row][col+2] = wv.z; Ws[row][col+3] = wv.w;
        *reinterpret_cast<float4*>(&Xs[row][col]) = x4[idx];
    }
    __syncthreads();

    u64 acc[4][4];
#pragma unroll
    for (int i = 0; i < 4; i++)
#pragma unroll
        for (int j = 0; j < 4; j++) acc[i][j] = 0ull;

#pragma unroll 8
    for (int e = 0; e < 64; e += 2) {
        u64 a[4], b[4];
#pragma unroll
        for (int i = 0; i < 4; i++) a[i] = lds2(&Xs[ty + 16 * i][e]);
#pragma unroll
        for (int j = 0; j < 4; j++) b[j] = lds2(&Ws[tx + 16 * j][e]);
#pragma unroll
        for (int i = 0; i < 4; i++)
#pragma unroll
            for (int j = 0; j < 4; j++) ffma2(acc[i][j], a[i], b[j]);
    }

#pragma unroll
    for (int i = 0; i < 4; i++) {
        int r  = r0 + ty + 16 * i;      // r = (n*L + l)*H + h
        int h  = r & (NHEAD - 1);
        int nl = r >> 4;
        int l  = nl & (LSEQ - 1);
        int n  = nl >> 11;
        int lo = l;
        if (compact) {
            if (!mask[n * LSEQ + l]) continue;   // masked key: drop row
            lo = g_pos[n * LSEQ + l];
        }
        float* o = O + (((size_t)(n * NHEAD + h) * LSEQ + lo) * HDIM);
#pragma unroll
        for (int j = 0; j < 4; j++) o[tx + 16 * j] = hadd2(acc[i][j]);
    }
}

__global__ __launch_bounds__(256) void qkv_proj_kernel(
    const float* __restrict__ values, const float* __restrict__ keys,
    const float* __restrict__ query, const int* __restrict__ mask,
    const float* __restrict__ Wv, const float* __restrict__ Wk,
    const float* __restrict__ Wq)
{
    __shared__ float Ws[64][66];
    __shared__ float Xs[64][64];
    int t  = threadIdx.x;
    int tx = t & 15, ty = t >> 4;
    int r0 = blockIdx.x * 64;
    proj_one(query,  Wq, g_q, mask, false, Ws, Xs, t, tx, ty, r0);
    proj_one(keys,   Wk, g_k, mask, true,  Ws, Xs, t, tx, ty, r0);
    proj_one(values, Wv, g_v, mask, true,  Ws, Xs, t, tx, ty, r0);
}

// ---------------------------------------------------------------------------
// Kernel B: flash attention over COMPACTED keys (all kept; no mask needed).
// One block = one (n,h), 64 q rows. K tiles of 32 over kept = g_cnt[n] keys;
// tail-tile slots past kept forced to -1e20 (exp -> exactly 0).
// Per thread: S tile 4x2, O tile 4x4 accumulated as f32x2 over j-pairs.
// V transposed in smem (Vt[d][j], stride 34 -> conflict-free paired reads).
// Scale = 1/sqrt(EMB) = 1/32.
// ---------------------------------------------------------------------------
__global__ __launch_bounds__(256) void attn_kernel()
{
    __shared__ float Qs[64][64];
    __shared__ float Ks[32][66];
    __shared__ float Vt[64][34];    // [d][j]
    __shared__ float Ss[64][34];    // even stride for paired j reads

    const float SCALE = 0.03125f;   // 1/sqrt(1024)

    int t  = threadIdx.x;
    int tx = t & 15, ty = t >> 4;
    int q0 = blockIdx.x * 64;
    int nh = blockIdx.y;
    int n  = nh >> 4;
    int h  = nh & 15;

    const size_t base = (size_t)nh * LSEQ * HDIM;
    const float* qb = g_q + base;
    const float* kb = g_k + base;
    const float* vb = g_v + base;
    const int kept = g_cnt[n];
    const int ntiles = (kept + 31) >> 5;

    // load Q tile (64x64), direct float4 smem stores
    {
        const float4* q4 = reinterpret_cast<const float4*>(qb + (size_t)q0 * HDIM);
        float4* qs4 = reinterpret_cast<float4*>(&Qs[0][0]);
#pragma unroll
        for (int i = 0; i < 4; i++) qs4[t + i * 256] = q4[t + i * 256];
    }

    float m_i[4], l_i[4];
    u64 o2[4][4];
#pragma unroll
    for (int i = 0; i < 4; i++) {
        m_i[i] = -3.0e38f;
        l_i[i] = 0.f;
#pragma unroll
        for (int j = 0; j < 4; j++) o2[i][j] = 0ull;
    }

    for (int kt = 0; kt < ntiles; kt++) {
        int k0 = kt * 32;
        __syncthreads();   // prior iteration done with Ks/Vt/Ss (orders Qs on iter 0)
        {
            const float4* k4 = reinterpret_cast<const float4*>(kb + (size_t)k0 * HDIM);
            const float4* v4 = reinterpret_cast<const float4*>(vb + (size_t)k0 * HDIM);
#pragma unroll
            for (int i = 0; i < 2; i++) {
                int idx = t + i * 256;      // 0..511 (32 rows x 16 f4)
                int row = idx >> 4;         // j (key slot in tile)
                int col = (idx & 15) << 2;  // d
                float4 kv, vv;
                if (k0 + row < kept) { kv = k4[idx]; vv = v4[idx]; }
                else { kv = make_float4(0,0,0,0); vv = kv; }
                Ks[row][col]   = kv.x; Ks[row][col+1] = kv.y;
                Ks[row][col+2] = kv.z; Ks[row][col+3] = kv.w;
                Vt[col][row]     = vv.x;    // transposed store
                Vt[col + 1][row] = vv.y;
                Vt[col + 2][row] = vv.z;
                Vt[col + 3][row] = vv.w;
            }
        }
        __syncthreads();

        // S = Q @ K^T  (4x2 per thread), f32x2 accumulation over e
        u64 s2[4][2];
#pragma unroll
        for (int i = 0; i < 4; i++) { s2[i][0] = 0ull; s2[i][1] = 0ull; }
#pragma unroll 8
        for (int e = 0; e < 64; e += 2) {
            u64 a[4], b0, b1;
#pragma unroll
            for (int i = 0; i < 4; i++) a[i] = lds2(&Qs[ty + 16 * i][e]);
            b0 = lds2(&Ks[tx][e]);
            b1 = lds2(&Ks[tx + 16][e]);
#pragma unroll
            for (int i = 0; i < 4; i++) {
                ffma2(s2[i][0], a[i], b0);
                ffma2(s2[i][1], a[i], b1);
            }
        }

        bool valid0 = (k0 + tx) < kept;
        bool valid1 = (k0 + tx + 16) < kept;
        float p[4][2], mt[4];
#pragma unroll
        for (int i = 0; i < 4; i++) {
            float v0 = valid0 ? hadd2(s2[i][0]) * SCALE : -1.0e20f;
            float v1 = valid1 ? hadd2(s2[i][1]) * SCALE : -1.0e20f;
            p[i][0] = v0; p[i][1] = v1;
            mt[i] = fmaxf(v0, v1);
        }
        // row max across the 16 lanes that share a q row
#pragma unroll
        for (int off = 8; off >= 1; off >>= 1) {
#pragma unroll
            for (int i = 0; i < 4; i++)
                mt[i] = fmaxf(mt[i], __shfl_xor_sync(0xffffffffu, mt[i], off));
        }
        float rsum[4];
#pragma unroll
        for (int i = 0; i < 4; i++) {
            float mn = fmaxf(m_i[i], mt[i]);
            float c  = __expf(m_i[i] - mn);
            m_i[i]   = mn;
            p[i][0]  = __expf(p[i][0] - mn);
            p[i][1]  = __expf(p[i][1] - mn);
            rsum[i]  = p[i][0] + p[i][1];
            l_i[i]  *= c;
            u64 cc = pack2(c, c);
#pragma unroll
            for (int j = 0; j < 4; j++) fmul2(o2[i][j], o2[i][j], cc);
        }
#pragma unroll
        for (int off = 8; off >= 1; off >>= 1) {
#pragma unroll
            for (int i = 0; i < 4; i++)
                rsum[i] += __shfl_xor_sync(0xffffffffu, rsum[i], off);
        }
#pragma unroll
        for (int i = 0; i < 4; i++) {
            l_i[i] += rsum[i];
            Ss[ty + 16 * i][tx]      = p[i][0];
            Ss[ty + 16 * i][tx + 16] = p[i][1];
        }
        __syncthreads();

        // O += P @ V : f32x2 over j-pairs. Thread's d cols = {tx+16c}.
#pragma unroll 4
        for (int j = 0; j < 32; j += 2) {
            u64 ps2[4], v2[4];
#pragma unroll
            for (int i = 0; i < 4; i++) ps2[i] = lds2(&Ss[ty + 16 * i][j]);
#pragma unroll
            for (int c4 = 0; c4 < 4; c4++) v2[c4] = lds2(&Vt[tx + 16 * c4][j]);
#pragma unroll
            for (int i = 0; i < 4; i++)
#pragma unroll
                for (int c4 = 0; c4 < 4; c4++) ffma2(o2[i][c4], ps2[i], v2[c4]);
        }
    }

    // epilogue: normalize, write to g_att in [n,l,e] layout
#pragma unroll
    for (int i = 0; i < 4; i++) {
        int qpos = q0 + ty + 16 * i;
        float inv = 1.0f / l_i[i];
        float* op = g_att + ((size_t)n * LSEQ + qpos) * EMB + h * HDIM;
#pragma unroll
        for (int c4 = 0; c4 < 4; c4++)
            op[tx + 16 * c4] = hadd2(o2[i][c4]) * inv;
    }
}

// ---------------------------------------------------------------------------
// Kernel C: output projection: out[r,c] = bo[c] + sum_e A[r,e]*Wo[c,e]
// A = g_att [4096,1024]. Block: 64x64 C tile, e tiles of 64, f32x2 reduction.
// ---------------------------------------------------------------------------
__global__ __launch_bounds__(256) void out_proj_kernel(
    const float* __restrict__ Wo, const float* __restrict__ bo,
    float* __restrict__ out)
{
    __shared__ float As[64][64];
    __shared__ float Bs[64][66];
    int t  = threadIdx.x;
    int tx = t & 15, ty = t >> 4;
    int c0 = blockIdx.x * 64;
    int r0 = blockIdx.y * 64;

    u64 acc[4][4];
#pragma unroll
    for (int i = 0; i < 4; i++)
#pragma unroll
        for (int j = 0; j < 4; j++) acc[i][j] = 0ull;

    for (int et = 0; et < EMB / 64; et++) {
        int e0 = et * 64;
        __syncthreads();
#pragma unroll
        for (int i = 0; i < 4; i++) {
            int idx  = t + i * 256;      // 0..1023 (64 rows x 16 f4)
            int row  = idx >> 4;
            int col4 = idx & 15;
            *reinterpret_cast<float4*>(&As[row][col4 * 4]) =
                *reinterpret_cast<const float4*>(
                    g_att + (size_t)(r0 + row) * EMB + e0 + col4 * 4);
            float4 bv = *reinterpret_cast<const float4*>(
                Wo + (size_t)(c0 + row) * EMB + e0 + col4 * 4);
            int col = col4 * 4;
            Bs[row][col]   = bv.x; Bs[row][col+1] = bv.y;
            Bs[row][col+2] = bv.z; Bs[row][col+3] = bv.w;
        }
        __syncthreads();
#pragma unroll 8
        for (int e = 0; e < 64; e += 2) {
            u64 a[4], b[4];
#pragma unroll
            for (int i = 0; i < 4; i++) a[i] = lds2(&As[ty + 16 * i][e]);
#pragma unroll
            for (int j = 0; j < 4; j++) b[j] = lds2(&Bs[tx + 16 * j][e]);
#pragma unroll
            for (int i = 0; i < 4; i++)
#pragma unroll
                for (int j = 0; j < 4; j++) ffma2(acc[i][j], a[i], b[j]);
        }
    }

#pragma unroll
    for (int i = 0; i < 4; i++) {
        int r = r0 + ty + 16 * i;
#pragma unroll
        for (int j = 0; j < 4; j++) {
            int c = c0 + tx + 16 * j;
            out[(size_t)r * EMB + c] = hadd2(acc[i][j]) + bo[c];
        }
    }
}

// ---------------------------------------------------------------------------
// Launch
// ---------------------------------------------------------------------------
extern "C" void kernel_launch(void* const* d_in, const int* in_sizes, int n_in,
                              void* d_out, int out_size)
{
    const float* values = (const float*)d_in[0];
    const float* keys   = (const float*)d_in[1];
    const float* query  = (const float*)d_in[2];
    const int*   mask   = (const int*)d_in[3];
    const float* Wv     = (const float*)d_in[4];
    const float* Wk     = (const float*)d_in[5];
    const float* Wq     = (const float*)d_in[6];
    const float* Wo     = (const float*)d_in[7];
    const float* bo     = (const float*)d_in[8];
    float* out = (float*)d_out;

    // 0: mask prefix-scan -> compact positions + counts
    mask_scan_kernel<<<NBATCH, 256>>>(mask);
    // A: 65536 rows / 64 per block (K/V written compacted)
    qkv_proj_kernel<<<(NBATCH * LSEQ * NHEAD) / 64, 256>>>(
        values, keys, query, mask, Wv, Wk, Wq);
    // B: (q tiles, n*h) over compacted keys
    attn_kernel<<<dim3(LSEQ / 64, NBATCH * NHEAD), 256>>>();
    // C: (col tiles, row tiles)
    out_proj_kernel<<<dim3(EMB / 64, (NBATCH * LSEQ) / 64), 256>>>(Wo, bo, out);
}

// round 17
// speedup vs baseline: 3.8276x; 2.2110x over previous
#include <cuda_runtime.h>

// Problem constants (fixed shapes from reference)
#define NBATCH 2
#define LSEQ   2048
#define EMB    1024
#define NHEAD  16
#define HDIM   64

typedef unsigned long long u64;
typedef unsigned int u32;

static __device__ float g_q[(size_t)NBATCH * NHEAD * LSEQ * HDIM];   // [n,h,l,d]
static __device__ float g_k[(size_t)NBATCH * NHEAD * LSEQ * HDIM];   // [n,h,lc,d] compacted
static __device__ float g_v[(size_t)NBATCH * NHEAD * LSEQ * HDIM];   // [n,h,lc,d] compacted
static __device__ float g_att[(size_t)NBATCH * LSEQ * EMB];          // [n,l,e]
static __device__ int   g_pos[NBATCH * LSEQ];                        // compact position per key
static __device__ int   g_cnt[NBATCH];                               // kept keys per batch

// ---- packed f32x2 helpers (used by qkv_proj; validated in R16) ----
__device__ __forceinline__ void ffma2(u64& d, u64 a, u64 b) {
    asm("fma.rn.f32x2 %0, %1, %2, %0;" : "+l"(d) : "l"(a), "l"(b));
}
__device__ __forceinline__ float hadd2(u64 v) {
    float x, y;
    asm("mov.b64 {%0,%1}, %2;" : "=f"(x), "=f"(y) : "l"(v));
    return x + y;
}
__device__ __forceinline__ u64 lds2(const float* p) {
    return *reinterpret_cast<const u64*>(p);
}

// ---- tf32 mma helpers ----
__device__ __forceinline__ u32 f2tf(float f) {      // round-to-nearest tf32 (bits in fp32 layout)
    u32 u; asm("cvt.rna.tf32.f32 %0, %1;" : "=r"(u) : "f"(f)); return u;
}
__device__ __forceinline__ float f2tff(float f) { return __uint_as_float(f2tf(f)); }
__device__ __forceinline__ void mma8(float& d0, float& d1, float& d2, float& d3,
                                     u32 a0, u32 a1, u32 a2, u32 a3,
                                     u32 b0, u32 b1) {
    asm("mma.sync.aligned.m16n8k8.row.col.f32.tf32.tf32.f32 "
        "{%0,%1,%2,%3},{%4,%5,%6,%7},{%8,%9},{%0,%1,%2,%3};"
        : "+f"(d0), "+f"(d1), "+f"(d2), "+f"(d3)
        : "r"(a0), "r"(a1), "r"(a2), "r"(a3), "r"(b0), "r"(b1));
}
__device__ __forceinline__ u32 fbits(float f) { return __float_as_uint(f); }

// ---------------------------------------------------------------------------
// Kernel 0: mask scan (unchanged from R16).
// ---------------------------------------------------------------------------
__global__ __launch_bounds__(256) void mask_scan_kernel(const int* __restrict__ mask)
{
    __shared__ int sums[256];
    int n = blockIdx.x;
    int t = threadIdx.x;
    int local[8], s = 0;
#pragma unroll
    for (int i = 0; i < 8; i++) {
        local[i] = (mask[n * LSEQ + t * 8 + i] != 0) ? 1 : 0;
        s += local[i];
    }
    sums[t] = s;
    __syncthreads();
    for (int off = 1; off < 256; off <<= 1) {
        int v = (t >= off) ? sums[t - off] : 0;
        __syncthreads();
        sums[t] += v;
        __syncthreads();
    }
    int run = sums[t] - s;
#pragma unroll
    for (int i = 0; i < 8; i++) {
        g_pos[n * LSEQ + t * 8 + i] = run;
        run += local[i];
    }
    if (t == 255) g_cnt[n] = sums[255];
}

// ---------------------------------------------------------------------------
// Kernel A: fused QKV projection (unchanged from R16; K/V compacted).
// ---------------------------------------------------------------------------
__device__ __forceinline__ void proj_one(
    const float* __restrict__ X, const float* __restrict__ W, float* __restrict__ O,
    const int* __restrict__ mask, bool compact,
    float (&Ws)[64][66], float (&Xs)[64][64],
    int t, int tx, int ty, int r0)
{
    __syncthreads();
    const float4* w4 = reinterpret_cast<const float4*>(W);
    const float4* x4 = reinterpret_cast<const float4*>(X + (size_t)r0 * HDIM);
#pragma unroll
    for (int i = 0; i < 4; i++) {
        int idx = t + i * 256;
        int row = idx >> 4;
        int col = (idx & 15) << 2;
        float4 wv = w4[idx];
        Ws[row][col]   = wv.x; Ws[row][col+1] = wv.y;
        Ws[row][col+2] = wv.z; Ws[row][col+3] = wv.w;
        *reinterpret_cast<float4*>(&Xs[row][col]) = x4[idx];
    }
    __syncthreads();

    u64 acc[4][4];
#pragma unroll
    for (int i = 0; i < 4; i++)
#pragma unroll
        for (int j = 0; j < 4; j++) acc[i][j] = 0ull;

#pragma unroll 8
    for (int e = 0; e < 64; e += 2) {
        u64 a[4], b[4];
#pragma unroll
        for (int i = 0; i < 4; i++) a[i] = lds2(&Xs[ty + 16 * i][e]);
#pragma unroll
        for (int j = 0; j < 4; j++) b[j] = lds2(&Ws[tx + 16 * j][e]);
#pragma unroll
        for (int i = 0; i < 4; i++)
#pragma unroll
            for (int j = 0; j < 4; j++) ffma2(acc[i][j], a[i], b[j]);
    }

#pragma unroll
    for (int i = 0; i < 4; i++) {
        int r  = r0 + ty + 16 * i;
        int h  = r & (NHEAD - 1);
        int nl = r >> 4;
        int l  = nl & (LSEQ - 1);
        int n  = nl >> 11;
        int lo = l;
        if (compact) {
            if (!mask[n * LSEQ + l]) continue;
            lo = g_pos[n * LSEQ + l];
        }
        float* o = O + (((size_t)(n * NHEAD + h) * LSEQ + lo) * HDIM);
#pragma unroll
        for (int j = 0; j < 4; j++) o[tx + 16 * j] = hadd2(acc[i][j]);
    }
}

__global__ __launch_bounds__(256) void qkv_proj_kernel(
    const float* __restrict__ values, const float* __restrict__ keys,
    const float* __restrict__ query, const int* __restrict__ mask,
    const float* __restrict__ Wv, const float* __restrict__ Wk,
    const float* __restrict__ Wq)
{
    __shared__ float Ws[64][66];
    __shared__ float Xs[64][64];
    int t  = threadIdx.x;
    int tx = t & 15, ty = t >> 4;
    int r0 = blockIdx.x * 64;
    proj_one(query,  Wq, g_q, mask, false, Ws, Xs, t, tx, ty, r0);
    proj_one(keys,   Wk, g_k, mask, true,  Ws, Xs, t, tx, ty, r0);
    proj_one(values, Wv, g_v, mask, true,  Ws, Xs, t, tx, ty, r0);
}

// ---------------------------------------------------------------------------
// Kernel B: flash attention over compacted keys using mma.sync m16n8k8 tf32.
// Block = (n,h), 64 q rows, 256 threads = 8 warps.
// Warp grid: wm = wid&3 (16 q rows each), wn = wid>>2.
//   S stage: wn selects 16-key half of the 32-key tile (2 n-tiles of 8).
//   PV stage: wn selects 32-d half (4 n-tiles of 8).
// Q fragments preloaded to registers (tf32). K/V tiles in smem (tf32).
// P round-trips through smem Ss (tf32). Softmax/accumulators fp32.
// Tail keys: K/V zero-filled, p forced to 0 (exact).
// ---------------------------------------------------------------------------
__global__ __launch_bounds__(256) void attn_kernel()
{
    __shared__ float Ks[32][68];      // [key][d], bank-safe for b-frag (4g+tg)
    __shared__ float Vs[32][72];      // [key][d], bank-safe for b-frag (8tg+g)
    __shared__ float Ss[64][36];      // [q][key-in-tile] P (tf32 bits)
    __shared__ float sm_max[2][64];
    __shared__ float sm_sum[2][64];

    const float SCALE = 0.03125f;     // 1/sqrt(1024)

    int t    = threadIdx.x;
    int lane = t & 31;
    int wid  = t >> 5;
    int wm   = wid & 3;
    int wn   = wid >> 2;
    int g    = lane >> 2;             // 0..7
    int tg   = lane & 3;              // 0..3
    int r0g  = 16 * wm + g;           // this thread's first q row (block-relative)

    int q0 = blockIdx.x * 64;
    int nh = blockIdx.y;
    int n  = nh >> 4;
    int h  = nh & 15;

    const size_t base = (size_t)nh * LSEQ * HDIM;
    const float* qb = g_q + base + (size_t)q0 * HDIM;
    const float* kb = g_k + base;
    const float* vb = g_v + base;
    const int kept   = g_cnt[n];
    const int ntiles = (kept + 31) >> 5;

    // Preload Q fragments (tf32) for rows r0g, r0g+8; 8 k-steps of 8 d.
    u32 qf[8][4];
    {
        const float* qr0 = qb + (size_t)r0g * HDIM;
        const float* qr1 = qb + (size_t)(r0g + 8) * HDIM;
#pragma unroll
        for (int k = 0; k < 8; k++) {
            int c = k * 8 + tg;
            qf[k][0] = f2tf(qr0[c]);
            qf[k][1] = f2tf(qr1[c]);
            qf[k][2] = f2tf(qr0[c + 4]);
            qf[k][3] = f2tf(qr1[c + 4]);
        }
    }

    float m_i[2] = {-3.0e38f, -3.0e38f};
    float l_i[2] = {0.f, 0.f};
    float o[4][4];                    // [d n-tile][c0..c3] fp32
#pragma unroll
    for (int i = 0; i < 4; i++)
#pragma unroll
        for (int j = 0; j < 4; j++) o[i][j] = 0.f;

    for (int kt = 0; kt < ntiles; kt++) {
        int k0 = kt * 32;
        __syncthreads();   // prior iteration done with Ks/Vs/Ss/sm_*
        {
            const float4* k4 = reinterpret_cast<const float4*>(kb + (size_t)k0 * HDIM);
            const float4* v4 = reinterpret_cast<const float4*>(vb + (size_t)k0 * HDIM);
#pragma unroll
            for (int i = 0; i < 2; i++) {
                int idx = t + i * 256;       // 0..511 (32 rows x 16 f4)
                int row = idx >> 4;
                int col = (idx & 15) << 2;
                float4 kv, vv;
                if (k0 + row < kept) { kv = k4[idx]; vv = v4[idx]; }
                else { kv = make_float4(0.f, 0.f, 0.f, 0.f); vv = kv; }
                Ks[row][col]   = f2tff(kv.x); Ks[row][col+1] = f2tff(kv.y);
                Ks[row][col+2] = f2tff(kv.z); Ks[row][col+3] = f2tff(kv.w);
                Vs[row][col]   = f2tff(vv.x); Vs[row][col+1] = f2tff(vv.y);
                Vs[row][col+2] = f2tff(vv.z); Vs[row][col+3] = f2tff(vv.w);
            }
        }
        __syncthreads();

        // S = Q @ K^T for this warp: 16 q rows x 16 keys (2 n-tiles), k over 64 d.
        float s[2][4];
#pragma unroll
        for (int nt = 0; nt < 2; nt++)
#pragma unroll
            for (int c = 0; c < 4; c++) s[nt][c] = 0.f;
#pragma unroll
        for (int k = 0; k < 8; k++) {
#pragma unroll
            for (int nt = 0; nt < 2; nt++) {
                int key = wn * 16 + nt * 8 + g;
                u32 b0 = fbits(Ks[key][k * 8 + tg]);
                u32 b1 = fbits(Ks[key][k * 8 + tg + 4]);
                mma8(s[nt][0], s[nt][1], s[nt][2], s[nt][3],
                     qf[k][0], qf[k][1], qf[k][2], qf[k][3], b0, b1);
            }
        }
        // scale
#pragma unroll
        for (int nt = 0; nt < 2; nt++)
#pragma unroll
            for (int c = 0; c < 4; c++) s[nt][c] *= SCALE;

        // partial row max (rows r0g and r0g+8); invalid cols hold 0 which is a
        // safe over-estimate candidate (their p is forced to 0 below).
        float mt0 = fmaxf(fmaxf(s[0][0], s[0][1]), fmaxf(s[1][0], s[1][1]));
        float mt1 = fmaxf(fmaxf(s[0][2], s[0][3]), fmaxf(s[1][2], s[1][3]));
        mt0 = fmaxf(mt0, __shfl_xor_sync(0xffffffffu, mt0, 1));
        mt0 = fmaxf(mt0, __shfl_xor_sync(0xffffffffu, mt0, 2));
        mt1 = fmaxf(mt1, __shfl_xor_sync(0xffffffffu, mt1, 1));
        mt1 = fmaxf(mt1, __shfl_xor_sync(0xffffffffu, mt1, 2));
        if (tg == 0) {
            sm_max[wn][r0g]     = mt0;
            sm_max[wn][r0g + 8] = mt1;
        }
        __syncthreads();

        float M0 = fmaxf(sm_max[0][r0g],     sm_max[1][r0g]);
        float M1 = fmaxf(sm_max[0][r0g + 8], sm_max[1][r0g + 8]);
        float mn0 = fmaxf(m_i[0], M0);
        float mn1 = fmaxf(m_i[1], M1);
        float c0 = __expf(m_i[0] - mn0);
        float c1 = __expf(m_i[1] - mn1);
        m_i[0] = mn0; m_i[1] = mn1;

        float rs0 = 0.f, rs1 = 0.f;
#pragma unroll
        for (int nt = 0; nt < 2; nt++) {
            int colb = wn * 16 + nt * 8 + 2 * tg;
            bool v0 = (k0 + colb)     < kept;
            bool v1 = (k0 + colb + 1) < kept;
            float p00 = v0 ? __expf(s[nt][0] - mn0) : 0.f;
            float p01 = v1 ? __expf(s[nt][1] - mn0) : 0.f;
            float p10 = v0 ? __expf(s[nt][2] - mn1) : 0.f;
            float p11 = v1 ? __expf(s[nt][3] - mn1) : 0.f;
            rs0 += p00 + p01;
            rs1 += p10 + p11;
            *reinterpret_cast<float2*>(&Ss[r0g][colb]) =
                make_float2(__uint_as_float(f2tf(p00)), __uint_as_float(f2tf(p01)));
            *reinterpret_cast<float2*>(&Ss[r0g + 8][colb]) =
                make_float2(__uint_as_float(f2tf(p10)), __uint_as_float(f2tf(p11)));
        }
        rs0 += __shfl_xor_sync(0xffffffffu, rs0, 1);
        rs0 += __shfl_xor_sync(0xffffffffu, rs0, 2);
        rs1 += __shfl_xor_sync(0xffffffffu, rs1, 1);
        rs1 += __shfl_xor_sync(0xffffffffu, rs1, 2);
        if (tg == 0) {
            sm_sum[wn][r0g]     = rs0;
            sm_sum[wn][r0g + 8] = rs1;
        }
        // rescale O accumulators
#pragma unroll
        for (int nt = 0; nt < 4; nt++) {
            o[nt][0] *= c0; o[nt][1] *= c0;
            o[nt][2] *= c1; o[nt][3] *= c1;
        }
        __syncthreads();   // sm_sum + Ss visible

        l_i[0] = l_i[0] * c0 + sm_sum[0][r0g]     + sm_sum[1][r0g];
        l_i[1] = l_i[1] * c1 + sm_sum[0][r0g + 8] + sm_sum[1][r0g + 8];

        // O += P @ V : 16 q rows x 32 d (this warp), k over 32 keys (4 steps).
#pragma unroll
        for (int ks = 0; ks < 4; ks++) {
            u32 a0 = fbits(Ss[r0g][ks * 8 + tg]);
            u32 a1 = fbits(Ss[r0g + 8][ks * 8 + tg]);
            u32 a2 = fbits(Ss[r0g][ks * 8 + tg + 4]);
            u32 a3 = fbits(Ss[r0g + 8][ks * 8 + tg + 4]);
#pragma unroll
            for (int nt = 0; nt < 4; nt++) {
                int d = wn * 32 + nt * 8 + g;
                u32 b0 = fbits(Vs[ks * 8 + tg][d]);
                u32 b1 = fbits(Vs[ks * 8 + tg + 4][d]);
                mma8(o[nt][0], o[nt][1], o[nt][2], o[nt][3],
                     a0, a1, a2, a3, b0, b1);
            }
        }
    }

    // epilogue: normalize, write to g_att [n,l,e]
    float inv0 = 1.0f / l_i[0];
    float inv1 = 1.0f / l_i[1];
    float* op0 = g_att + ((size_t)n * LSEQ + q0 + r0g) * EMB + h * HDIM;
    float* op1 = g_att + ((size_t)n * LSEQ + q0 + r0g + 8) * EMB + h * HDIM;
#pragma unroll
    for (int nt = 0; nt < 4; nt++) {
        int d = wn * 32 + nt * 8 + 2 * tg;
        *reinterpret_cast<float2*>(op0 + d) = make_float2(o[nt][0] * inv0, o[nt][1] * inv0);
        *reinterpret_cast<float2*>(op1 + d) = make_float2(o[nt][2] * inv1, o[nt][3] * inv1);
    }
}

// ---------------------------------------------------------------------------
// Kernel C: output projection via mma tf32: out[r,c] = bo[c] + sum_e A[r,e]*Wo[c,e]
// Block: 64x64 C tile, 8 warps (wm = wid&3 -> 16 rows, wn = wid>>2 -> 32 cols).
// ---------------------------------------------------------------------------
__global__ __launch_bounds__(256) void out_proj_kernel(
    const float* __restrict__ Wo, const float* __restrict__ bo,
    float* __restrict__ out)
{
    __shared__ float As[64][68];
    __shared__ float Bs[64][68];

    int t    = threadIdx.x;
    int lane = t & 31;
    int wid  = t >> 5;
    int wm   = wid & 3;
    int wn   = wid >> 2;
    int g    = lane >> 2;
    int tg   = lane & 3;
    int c0 = blockIdx.x * 64;
    int r0 = blockIdx.y * 64;

    float acc[4][4];
#pragma unroll
    for (int i = 0; i < 4; i++)
#pragma unroll
        for (int j = 0; j < 4; j++) acc[i][j] = 0.f;

    for (int et = 0; et < EMB / 64; et++) {
        int e0 = et * 64;
        __syncthreads();
#pragma unroll
        for (int i = 0; i < 4; i++) {
            int idx  = t + i * 256;
            int row  = idx >> 4;
            int col  = (idx & 15) << 2;
            float4 av = *reinterpret_cast<const float4*>(
                g_att + (size_t)(r0 + row) * EMB + e0 + col);
            As[row][col]   = f2tff(av.x); As[row][col+1] = f2tff(av.y);
            As[row][col+2] = f2tff(av.z); As[row][col+3] = f2tff(av.w);
            float4 bv = *reinterpret_cast<const float4*>(
                Wo + (size_t)(c0 + row) * EMB + e0 + col);
            Bs[row][col]   = f2tff(bv.x); Bs[row][col+1] = f2tff(bv.y);
            Bs[row][col+2] = f2tff(bv.z); Bs[row][col+3] = f2tff(bv.w);
        }
        __syncthreads();

#pragma unroll
        for (int k = 0; k < 8; k++) {
            u32 a0 = fbits(As[16 * wm + g][k * 8 + tg]);
            u32 a1 = fbits(As[16 * wm + g + 8][k * 8 + tg]);
            u32 a2 = fbits(As[16 * wm + g][k * 8 + tg + 4]);
            u32 a3 = fbits(As[16 * wm + g + 8][k * 8 + tg + 4]);
#pragma unroll
            for (int nt = 0; nt < 4; nt++) {
                int c = wn * 32 + nt * 8 + g;
                u32 b0 = fbits(Bs[c][k * 8 + tg]);
                u32 b1 = fbits(Bs[c][k * 8 + tg + 4]);
                mma8(acc[nt][0], acc[nt][1], acc[nt][2], acc[nt][3],
                     a0, a1, a2, a3, b0, b1);
            }
        }
    }

    int rr0 = r0 + 16 * wm + g;
    int rr1 = rr0 + 8;
#pragma unroll
    for (int nt = 0; nt < 4; nt++) {
        int c = c0 + wn * 32 + nt * 8 + 2 * tg;
        float b0 = bo[c], b1 = bo[c + 1];
        *reinterpret_cast<float2*>(out + (size_t)rr0 * EMB + c) =
            make_float2(acc[nt][0] + b0, acc[nt][1] + b1);
        *reinterpret_cast<float2*>(out + (size_t)rr1 * EMB + c) =
            make_float2(acc[nt][2] + b0, acc[nt][3] + b1);
    }
}

// ---------------------------------------------------------------------------
// Launch
// ---------------------------------------------------------------------------
extern "C" void kernel_launch(void* const* d_in, const int* in_sizes, int n_in,
                              void* d_out, int out_size)
{
    const float* values = (const float*)d_in[0];
    const float* keys   = (const float*)d_in[1];
    const float* query  = (const float*)d_in[2];
    const int*   mask   = (const int*)d_in[3];
    const float* Wv     = (const float*)d_in[4];
    const float* Wk     = (const float*)d_in[5];
    const float* Wq     = (const float*)d_in[6];
    const float* Wo     = (const float*)d_in[7];
    const float* bo     = (const float*)d_in[8];
    float* out = (float*)d_out;

    // 0: mask prefix-scan -> compact positions + counts
    mask_scan_kernel<<<NBATCH, 256>>>(mask);
    // A: QKV projection (K/V written compacted)
    qkv_proj_kernel<<<(NBATCH * LSEQ * NHEAD) / 64, 256>>>(
        values, keys, query, mask, Wv, Wk, Wq);
    // B: attention (q tiles, n*h) over compacted keys — tensor-core path
    attn_kernel<<<dim3(LSEQ / 64, NBATCH * NHEAD), 256>>>();
    // C: output projection — tensor-core path
    out_proj_kernel<<<dim3(EMB / 64, (NBATCH * LSEQ) / 64), 256>>>(Wo, bo, out);
}